// round 15
// baseline (speedup 1.0000x reference)
#include <cuda_runtime.h>
#include <stdint.h>

// PackBits: word w has bit p = signbit(x[32*w + (p^7)])
//   (numpy packbits MSB-first per byte + little-endian uint32 view
//    => element k lands at bit position k^7 within its word.)
// Harness readback: reference uint32 words reinterpreted as SIGNED int32,
// value-compared -> we store (float)(int32)word.
//
// Scheme: lane l loads element 32*w + (l^7) -> warp load = one 128B row
//         (^7 permutes within 8-lane groups; sector pattern unchanged).
//         __ballot_sync((int)v < 0) IS the packed word (bit p = lane p).
//         Each warp makes WPW=32 consecutive words; ballot j's uniform result
//         is kept by lane j, then one coalesced 128B float store.
//
// Two-phase body: all 32 LDGs batched into a register array (MLP=32 per
// warp) before the 32 warp-synchronizing ballots. Streaming cache hints
// since neither input nor output is reused.
//
// CONVERGED at the chip's streaming ceiling (LTS fabric ~6300 B/cyc,
// path-independent => ~6.7-6.85 TB/s at the memory-saturated clock).
// Identical-binary samples: 78.3 / 83.9 / 82.4 / 82.4 / 78.2 us
// (HBM 6712/6847/6710/6695/6809 GB/s). Best = 78.2 us, within 1.3% of the
// 528 MiB / 6.85 TB/s traffic floor (~77.2 us).
// Closed-out alternatives:
//   - interleaved load/vote (R7): same plateau, worse tail
//   - looped pipeline (R9): ALU 71% -> 6210 GB/s
//   - straight-line high-ILP (R10): occ 42% -> 4106 GB/s
//   - LDG.128 + nibble/shfl assembly: ballot no longer per-word; ~7 ALU +
//     3 chained SHFL.BFLY per 16B -> R9 failure mode
//   - cp.async/TMA: path-independent at the LTS cap
// Traffic is irreducible (512 MiB read + 16 MiB write, one touch each).

#define WPW 32  // words per warp

__global__ __launch_bounds__(256) void packbits_kernel(
    const unsigned int* __restrict__ x,  // fp32 bits: sign = bit 31
    float* __restrict__ out,
    int nwords, long long nelem)
{
    const int lane = threadIdx.x & 31;
    const long long warp_global = (long long)((blockIdx.x * blockDim.x + threadIdx.x) >> 5);
    const long long word0 = warp_global * WPW;
    if (word0 >= nwords) return;

    const int src_lane = lane ^ 7;

    if (word0 + WPW <= (long long)nwords && (word0 + WPW) * 32 <= nelem) {
        // Fast path: full tile.
        const unsigned int* p = x + word0 * 32 + src_lane;

        // Phase 1: batch all loads -> MLP = 32 in flight per warp.
        unsigned int v[WPW];
#pragma unroll
        for (int j = 0; j < WPW; j++)
            v[j] = __ldcs(p + (long long)j * 32);

        // Phase 2: ballots on register-resident values.
        unsigned int mine = 0;
#pragma unroll
        for (int j = 0; j < WPW; j++) {
            unsigned int w = __ballot_sync(0xFFFFFFFFu, (int)v[j] < 0);
            if (lane == j) mine = w;
        }
        __stcs(&out[word0 + lane], (float)(int)mine);  // coalesced 128B row
    } else {
        // Tail path (not hit for N=2^27; kept for generality).
        for (int j = 0; j < WPW; j++) {
            long long wi = word0 + j;
            if (wi >= nwords) break;
            long long idx = wi * 32 + src_lane;
            unsigned int v = (idx < nelem) ? x[idx] : 0u;
            unsigned int w = __ballot_sync(0xFFFFFFFFu, (int)v < 0);
            if (lane == 0) out[wi] = (float)(int)w;
        }
    }
}

extern "C" void kernel_launch(void* const* d_in, const int* in_sizes, int n_in,
                              void* d_out, int out_size)
{
    const unsigned int* x = (const unsigned int*)d_in[0];
    float* out = (float*)d_out;
    long long n = (long long)in_sizes[0];
    int nwords = out_size;  // ceil(n/32); here n = 2^27 -> nwords = 2^22

    const int threads = 256;                           // 8 warps/block
    const int words_per_block = (threads / 32) * WPW;  // 256 words/block
    int blocks = (int)((nwords + (long long)words_per_block - 1) / words_per_block);

    packbits_kernel<<<blocks, threads>>>(x, out, nwords, n);
}